// round 16
// baseline (speedup 1.0000x reference)
#include <cuda_runtime.h>
#include <cuda_bf16.h>
#include <math.h>

#define DIMC 256
#define NHEADS 8
#define HEADD 32
#define KEYD 16
#define HQKV 512
#define NB 16
#define NPIX 1024
#define EPSV 1e-5f
// score scale folded with log2(e): softmax computed in exp2 domain
#define ATTN_SCALE_LOG2 (0.25f * 1.44269504088896f)

// Scratch (allocation-free rule: __device__ globals)
__device__ float g_qkv_buf[(size_t)NB * HQKV * NPIX];   // 33.5 MB: qkv[b][o][p]
__device__ float g_att_buf[(size_t)NB * DIMC * NPIX];   // 16.8 MB
// Per (b,h) plane (64*NPIX bf16):
//   [0:16384)      kT_hi [1024 pix][16 dims]
//   [16384:32768)  kT_lo [1024 pix][16 dims]
//   [32768:65536)  v_hi  [32 dims][1024 pix]
__device__ __nv_bfloat16 g_kv_bf[(size_t)NB * NHEADS * 64 * NPIX];

// ---------------------------------------------------------------------------
#define MMA16816(c, a, b0v, b1v)                                              \
    asm volatile(                                                             \
        "mma.sync.aligned.m16n8k16.row.col.f32.bf16.bf16.f32 "                \
        "{%0,%1,%2,%3}, {%4,%5,%6,%7}, {%8,%9}, {%0,%1,%2,%3};"               \
        : "+f"((c)[0]), "+f"((c)[1]), "+f"((c)[2]), "+f"((c)[3])              \
        : "r"((a)[0]), "r"((a)[1]), "r"((a)[2]), "r"((a)[3]),                 \
          "r"(b0v), "r"(b1v))

// D = A*B + Z (separate zero source quad; removes per-tile accumulator init)
#define MMA16816_Z(d, a, b0v, b1v, z)                                         \
    asm volatile(                                                             \
        "mma.sync.aligned.m16n8k16.row.col.f32.bf16.bf16.f32 "                \
        "{%0,%1,%2,%3}, {%4,%5,%6,%7}, {%8,%9}, {%10,%11,%12,%13};"           \
        : "=f"((d)[0]), "=f"((d)[1]), "=f"((d)[2]), "=f"((d)[3])              \
        : "r"((a)[0]), "r"((a)[1]), "r"((a)[2]), "r"((a)[3]),                 \
          "r"(b0v), "r"(b1v),                                                 \
          "f"((z)[0]), "f"((z)[1]), "f"((z)[2]), "f"((z)[3]))

#define CP_ASYNC16(dst32, src)                                                \
    asm volatile("cp.async.cg.shared.global [%0], [%1], 16;"                  \
                 :: "r"(dst32), "l"(src))
#define CP_COMMIT asm volatile("cp.async.commit_group;")
#define CP_WAIT0  asm volatile("cp.async.wait_group 0;" ::: "memory")

// Split-pack: hi = bf16(v), lo = bf16(v - hi); element0 in low 16 bits.
__device__ __forceinline__ unsigned pack_hi2(float v0, float v1, unsigned& lo_out) {
    __nv_bfloat162 hh, ll;
    hh.x = __float2bfloat16_rn(v0);
    hh.y = __float2bfloat16_rn(v1);
    ll.x = __float2bfloat16_rn(v0 - __bfloat162float(hh.x));
    ll.y = __float2bfloat16_rn(v1 - __bfloat162float(hh.y));
    lo_out = *(unsigned*)&ll;
    return *(unsigned*)&hh;
}

__device__ __forceinline__ unsigned pack_bf16x2(float lo, float hi) {
    unsigned r;
    asm("cvt.rn.bf16x2.f32 %0, %1, %2;" : "=r"(r) : "f"(hi), "f"(lo));
    return r;
}

__device__ __forceinline__ float exp2a(float x) {
    float y;
    asm("ex2.approx.f32 %0, %1;" : "=f"(y) : "f"(x));
    return y;
}

// ---------------------------------------------------------------------------
// Tensor-core GEMM + BN, double-buffered smem, 2 CTAs/SM (frozen from R13).
// W hi/lo + In hi/lo, 3-MMA split. If kvbuf != nullptr: emits kT hi/lo
// (transposed) and v hi bf16 planes.
// ---------------------------------------------------------------------------
__global__ void __launch_bounds__(256, 2)
gemm_bn_kernel(const float* __restrict__ W,
               const float* __restrict__ In,
               float* __restrict__ Out,
               int M,
               const float* __restrict__ gam,
               const float* __restrict__ bet,
               const float* __restrict__ mu,
               const float* __restrict__ var,
               __nv_bfloat16* __restrict__ kvbuf) {
    __shared__ __align__(16) __nv_bfloat16 Ws_h[2][64][24], Ws_l[2][64][24];
    __shared__ __align__(16) __nv_bfloat16 Bs_h[2][128][24], Bs_l[2][128][24];

    const int b = blockIdx.z;
    const int oBase = blockIdx.y * 64;
    const int pBase = blockIdx.x * 128;
    const int tid = threadIdx.x;
    const int warp = tid >> 5;
    const int lane = tid & 31;
    const int gr = lane >> 2;
    const int tc = lane & 3;
    const int o0 = (warp >> 1) * 16;
    const int p0 = (warp & 1) * 64;

    const float* inb = In + (size_t)b * DIMC * NPIX;

    const int sw_o = tid >> 2;
    const int sw_c = (tid & 3) * 4;
    const int sb_p = tid & 127;
    const int sb_cp = tid >> 7;

    float wreg[4];
    float inreg[8];

    // ---- prefetch + commit kstep 0 ----
    *(float4*)wreg = *(const float4*)&W[(size_t)(oBase + sw_o) * DIMC + sw_c];
#pragma unroll
    for (int j = 0; j < 4; j++) {
        int c = 2 * (sb_cp + 2 * j);
        inreg[2 * j]     = inb[(size_t)c * NPIX + pBase + sb_p];
        inreg[2 * j + 1] = inb[(size_t)(c + 1) * NPIX + pBase + sb_p];
    }
#pragma unroll
    for (int j = 0; j < 2; j++) {
        unsigned lo, hi = pack_hi2(wreg[2 * j], wreg[2 * j + 1], lo);
        *(unsigned*)&Ws_h[0][sw_o][sw_c + 2 * j] = hi;
        *(unsigned*)&Ws_l[0][sw_o][sw_c + 2 * j] = lo;
    }
#pragma unroll
    for (int j = 0; j < 4; j++) {
        int c = 2 * (sb_cp + 2 * j);
        unsigned lo, hi = pack_hi2(inreg[2 * j], inreg[2 * j + 1], lo);
        *(unsigned*)&Bs_h[0][sb_p][c] = hi;
        *(unsigned*)&Bs_l[0][sb_p][c] = lo;
    }
    __syncthreads();

    float C[8][4];
#pragma unroll
    for (int nt = 0; nt < 8; nt++)
#pragma unroll
        for (int r = 0; r < 4; r++) C[nt][r] = 0.f;

    for (int ks = 0; ks < 16; ks++) {
        const int cur = ks & 1;
        if (ks < 15) {
            int k0 = (ks + 1) * 16;
            *(float4*)wreg = *(const float4*)&W[(size_t)(oBase + sw_o) * DIMC + k0 + sw_c];
#pragma unroll
            for (int j = 0; j < 4; j++) {
                int c = k0 + 2 * (sb_cp + 2 * j);
                inreg[2 * j]     = inb[(size_t)c * NPIX + pBase + sb_p];
                inreg[2 * j + 1] = inb[(size_t)(c + 1) * NPIX + pBase + sb_p];
            }
        }

        unsigned ah[4], al[4];
        ah[0] = *(const unsigned*)&Ws_h[cur][o0 + gr][2 * tc];
        ah[1] = *(const unsigned*)&Ws_h[cur][o0 + gr + 8][2 * tc];
        ah[2] = *(const unsigned*)&Ws_h[cur][o0 + gr][2 * tc + 8];
        ah[3] = *(const unsigned*)&Ws_h[cur][o0 + gr + 8][2 * tc + 8];
        al[0] = *(const unsigned*)&Ws_l[cur][o0 + gr][2 * tc];
        al[1] = *(const unsigned*)&Ws_l[cur][o0 + gr + 8][2 * tc];
        al[2] = *(const unsigned*)&Ws_l[cur][o0 + gr][2 * tc + 8];
        al[3] = *(const unsigned*)&Ws_l[cur][o0 + gr + 8][2 * tc + 8];
#pragma unroll
        for (int nt = 0; nt < 8; nt++) {
            int p = p0 + nt * 8 + gr;
            unsigned bh0 = *(const unsigned*)&Bs_h[cur][p][2 * tc];
            unsigned bh1 = *(const unsigned*)&Bs_h[cur][p][2 * tc + 8];
            unsigned bl0 = *(const unsigned*)&Bs_l[cur][p][2 * tc];
            unsigned bl1 = *(const unsigned*)&Bs_l[cur][p][2 * tc + 8];
            MMA16816(C[nt], ah, bh0, bh1);
            MMA16816(C[nt], ah, bl0, bl1);
            MMA16816(C[nt], al, bh0, bh1);
        }

        if (ks < 15) {
            const int nxt = cur ^ 1;
#pragma unroll
            for (int j = 0; j < 2; j++) {
                unsigned lo, hi = pack_hi2(wreg[2 * j], wreg[2 * j + 1], lo);
                *(unsigned*)&Ws_h[nxt][sw_o][sw_c + 2 * j] = hi;
                *(unsigned*)&Ws_l[nxt][sw_o][sw_c + 2 * j] = lo;
            }
#pragma unroll
            for (int j = 0; j < 4; j++) {
                int c = 2 * (sb_cp + 2 * j);
                unsigned lo, hi = pack_hi2(inreg[2 * j], inreg[2 * j + 1], lo);
                *(unsigned*)&Bs_h[nxt][sb_p][c] = hi;
                *(unsigned*)&Bs_l[nxt][sb_p][c] = lo;
            }
            __syncthreads();
        }
    }

    // ---- epilogue: BN + store (+ optional kv plane emission) ----
    const int oG0 = oBase + o0 + gr;
    const int oG1 = oG0 + 8;
    float inv0 = rsqrtf(var[oG0] + EPSV) * gam[oG0];
    float add0 = bet[oG0] - mu[oG0] * inv0;
    float inv1 = rsqrtf(var[oG1] + EPSV) * gam[oG1];
    float add1 = bet[oG1] - mu[oG1] * inv1;

#pragma unroll
    for (int nt = 0; nt < 8; nt++) {
        int p = pBase + p0 + nt * 8 + 2 * tc;
        float2 r0, r1;
        r0.x = C[nt][0] * inv0 + add0;
        r0.y = C[nt][1] * inv0 + add0;
        r1.x = C[nt][2] * inv1 + add1;
        r1.y = C[nt][3] * inv1 + add1;
        *(float2*)&Out[((size_t)b * M + oG0) * NPIX + p] = r0;
        *(float2*)&Out[((size_t)b * M + oG1) * NPIX + p] = r1;

        if (kvbuf != nullptr) {
#pragma unroll
            for (int rr = 0; rr < 2; rr++) {
                int o = rr ? oG1 : oG0;
                float vx = rr ? r1.x : r0.x;
                float vy = rr ? r1.y : r0.y;
                int r64 = o & 63;
                if (r64 >= 16) {
                    int h = o >> 6;
                    __nv_bfloat16* hb = kvbuf + ((size_t)b * NHEADS + h) * (64 * NPIX);
                    if (r64 >= 32) {          // v: hi plane [32][1024]
                        unsigned hv = pack_bf16x2(vx, vy);
                        *(unsigned*)&hb[32768 + (size_t)(r64 - 32) * NPIX + p] = hv;
                    } else {                  // k: transposed hi/lo planes [1024][16]
                        int d = r64 - 16;
                        __nv_bfloat16 h0 = __float2bfloat16_rn(vx);
                        __nv_bfloat16 l0 = __float2bfloat16_rn(vx - __bfloat162float(h0));
                        __nv_bfloat16 h1 = __float2bfloat16_rn(vy);
                        __nv_bfloat16 l1 = __float2bfloat16_rn(vy - __bfloat162float(h1));
                        hb[(size_t)p * 16 + d] = h0;
                        hb[(size_t)(p + 1) * 16 + d] = h1;
                        hb[16384 + (size_t)p * 16 + d] = l0;
                        hb[16384 + (size_t)(p + 1) * 16 + d] = l1;
                    }
                }
            }
        }
    }
}

// ---------------------------------------------------------------------------
// Attention, no online softmax (bounded scores). 512 threads / 16 warps per
// CTA, ONE 16-query tile per warp -> ~55 regs/thread -> 2 CTAs/SM -> 8
// warps/SMSP (2x R13) to cover LDS->MMA->exp2->MMA dependency latency.
// 64-key double-buffered chunks via cp.async (1 x 16B per thread per chunk).
// ---------------------------------------------------------------------------
struct KVBuf {
    __nv_bfloat16 Ks_h[64][24];   // 3072 B
    __nv_bfloat16 Ks_l[64][24];   // 3072 B
    __nv_bfloat16 Vt_h[32][72];   // 4608 B
};
#define KVBUF_BYTES 10752

__global__ void __launch_bounds__(512, 2)
attn_kernel(const float* __restrict__ qkv,
            const __nv_bfloat16* __restrict__ kvbf,
            float* __restrict__ att) {
    __shared__ __align__(16) char smem_raw[KVBUF_BYTES + 16 * 256 * 4];
    KVBuf* bufs[2];
    bufs[0] = (KVBuf*)smem_raw;
    bufs[1] = (KVBuf*)(smem_raw + KVBUF_BYTES);
    float (*Qs)[256] = (float(*)[256])(smem_raw + KVBUF_BYTES);   // alias buf 1

    const int blk = blockIdx.x;      // 0..511
    const int bh = blk >> 2;
    const int qq = blk & 3;
    const int b = bh >> 3;
    const int h = bh & 7;
    const float* base = qkv + ((size_t)b * HQKV + h * 64) * NPIX;
    const __nv_bfloat16* kvh = kvbf + ((size_t)b * NHEADS + h) * (64 * NPIX);
    float* ob = att + ((size_t)b * DIMC + h * HEADD) * NPIX;

    const int tid = threadIdx.x;     // 0..511
    const int warp = tid >> 5;       // 0..15, one q-tile each
    const int lane = tid & 31;
    const int gr = lane >> 2;
    const int tc = lane & 3;
    const int qBase = qq * 256;

    // cp.async task mapping: exactly one 16B copy per thread per chunk.
    //   tid   0..127 : Ks_h  key=(tid&127)>>1, dim half=(tid&1)*8
    //   tid 128..255 : Ks_l  same
    //   tid 256..511 : Vt_h  d=(tid-256)>>3, key granule=tid&7
    const int kkey = (tid & 127) >> 1;
    const int kho = (tid & 1) * 8;
    const int vd = (tid >> 3) & 31;
    const int vg = tid & 7;

    // ---- issue chunk 0 into buf0 (doesn't touch Qs alias = buf1) ----
    if (tid < 256) {
        const __nv_bfloat16* ksrc = kvh + ((tid < 128) ? 0 : 16384)
                                  + (size_t)kkey * 16 + kho;
        unsigned kdst = (unsigned)__cvta_generic_to_shared(
            (tid < 128) ? &bufs[0]->Ks_h[kkey][kho] : &bufs[0]->Ks_l[kkey][kho]);
        CP_ASYNC16(kdst, ksrc);
    } else {
        unsigned vdst = (unsigned)__cvta_generic_to_shared(&bufs[0]->Vt_h[vd][vg * 8]);
        CP_ASYNC16(vdst, kvh + 32768 + (size_t)vd * NPIX + vg * 8);
    }
    CP_COMMIT;

    // ---- stage Q (scaled into exp2 domain) into aliased region ----
    for (int idx = tid; idx < 16 * 256; idx += 512) {
        int c = idx >> 8, p = idx & 255;
        Qs[c][p] = base[c * NPIX + qBase + p] * ATTN_SCALE_LOG2;
    }
    __syncthreads();

    // ---- Q fragment (bf16 hi only): warp's 16 queries ----
    unsigned qf[4];
#pragma unroll
    for (int r = 0; r < 4; r++) {
        int row = warp * 16 + gr + ((r & 1) ? 8 : 0);
        int k0 = 2 * tc + ((r & 2) ? 8 : 0);
        qf[r] = pack_bf16x2(Qs[k0][row], Qs[k0 + 1][row]);
    }
    CP_WAIT0;
    __syncthreads();   // chunk0 visible; all warps done reading Qs

    float zq[4] = {0.f, 0.f, 0.f, 0.f};
    float lp0 = 0.f, lp1 = 0.f;     // per-thread partial sums of P (row halves)
    float O[4][4];
#pragma unroll
    for (int dt = 0; dt < 4; dt++)
#pragma unroll
        for (int r = 0; r < 4; r++) O[dt][r] = 0.f;

    for (int kb = 0; kb < 16; kb++) {
        const KVBuf* cb = bufs[kb & 1];
        const bool more = (kb < 15);
        // ---- issue next chunk into other buffer (async, overlaps MMA) ----
        if (more) {
            KVBuf* nb = bufs[(kb + 1) & 1];
            if (tid < 256) {
                const size_t koff = (size_t)((kb + 1) * 64 + kkey) * 16 + kho;
                const __nv_bfloat16* ksrc = kvh + ((tid < 128) ? 0 : 16384) + koff;
                unsigned kdst = (unsigned)__cvta_generic_to_shared(
                    (tid < 128) ? &nb->Ks_h[kkey][kho] : &nb->Ks_l[kkey][kho]);
                CP_ASYNC16(kdst, ksrc);
            } else {
                unsigned vdst = (unsigned)__cvta_generic_to_shared(&nb->Vt_h[vd][vg * 8]);
                CP_ASYNC16(vdst, kvh + 32768 + (size_t)vd * NPIX + (kb + 1) * 64 + vg * 8);
            }
            CP_COMMIT;
        }

        // ---- 4 independent 16-key blocks: QK -> exp2 -> pack -> AV ----
#pragma unroll
        for (int ks = 0; ks < 4; ks++) {
            float S[2][4];   // [j][reg], j = 8-key ntile within this block
#pragma unroll
            for (int j = 0; j < 2; j++) {
                const int krow = (2 * ks + j) * 8 + gr;
                unsigned bh0 = *(const unsigned*)&cb->Ks_h[krow][2 * tc];
                unsigned bh1 = *(const unsigned*)&cb->Ks_h[krow][2 * tc + 8];
                unsigned bl0 = *(const unsigned*)&cb->Ks_l[krow][2 * tc];
                unsigned bl1 = *(const unsigned*)&cb->Ks_l[krow][2 * tc + 8];
                MMA16816_Z(S[j], qf, bh0, bh1, zq);
                MMA16816(S[j], qf, bl0, bl1);
            }

            unsigned ph[4];
#pragma unroll
            for (int j = 0; j < 2; j++) {
                S[j][0] = exp2a(S[j][0]);
                S[j][1] = exp2a(S[j][1]);
                S[j][2] = exp2a(S[j][2]);
                S[j][3] = exp2a(S[j][3]);
                lp0 += S[j][0] + S[j][1];
                lp1 += S[j][2] + S[j][3];
            }
            ph[0] = pack_bf16x2(S[0][0], S[0][1]);
            ph[1] = pack_bf16x2(S[0][2], S[0][3]);
            ph[2] = pack_bf16x2(S[1][0], S[1][1]);
            ph[3] = pack_bf16x2(S[1][2], S[1][3]);

#pragma unroll
            for (int dt = 0; dt < 4; dt++) {
                const int dr = dt * 8 + gr;
                const int kc = ks * 16 + 2 * tc;
                unsigned vh0 = *(const unsigned*)&cb->Vt_h[dr][kc];
                unsigned vh1 = *(const unsigned*)&cb->Vt_h[dr][kc + 8];
                MMA16816(O[dt], ph, vh0, vh1);
            }
        }

        // ---- wait for next chunk copies, then flip ----
        if (more) {
            CP_WAIT0;
            __syncthreads();
        }
    }

    // ---- epilogue: one shfl-reduce of l per row, normalize, store ----
    lp0 += __shfl_xor_sync(0xffffffffu, lp0, 1);
    lp0 += __shfl_xor_sync(0xffffffffu, lp0, 2);
    lp1 += __shfl_xor_sync(0xffffffffu, lp1, 1);
    lp1 += __shfl_xor_sync(0xffffffffu, lp1, 2);
    float r0 = 1.f / lp0;
    float r1 = 1.f / lp1;
    int q0 = qBase + warp * 16 + gr;
    int q1 = q0 + 8;
#pragma unroll
    for (int dt = 0; dt < 4; dt++) {
        int d = dt * 8 + 2 * tc;
        ob[(size_t)d * NPIX + q0]       = O[dt][0] * r0;
        ob[(size_t)(d + 1) * NPIX + q0] = O[dt][1] * r0;
        ob[(size_t)d * NPIX + q1]       = O[dt][2] * r1;
        ob[(size_t)(d + 1) * NPIX + q1] = O[dt][3] * r1;
    }
}

// ---------------------------------------------------------------------------
// Depthwise 3x3 conv on v_img + BN, added into attended buffer in-place.
// ---------------------------------------------------------------------------
__global__ void pos_conv_kernel(const float* __restrict__ qkv,
                                float* __restrict__ att,
                                const float* __restrict__ wpos,
                                const float* __restrict__ gam,
                                const float* __restrict__ bet,
                                const float* __restrict__ mu,
                                const float* __restrict__ var) {
    int idx = blockIdx.x * blockDim.x + threadIdx.x;
    if (idx >= NB * DIMC * NPIX) return;
    int p = idx & 1023;
    int ch = (idx >> 10) & 255;
    int b = idx >> 18;
    int y = p >> 5, x = p & 31;
    int o = ((ch >> 5) * 64) + 32 + (ch & 31);
    const float* vrow = qkv + ((size_t)b * HQKV + o) * NPIX;
    const float* wp = wpos + ch * 9;

    float acc = 0.f;
#pragma unroll
    for (int dy = 0; dy < 3; dy++) {
        int yy = y + dy - 1;
        if (yy < 0 || yy > 31) continue;
#pragma unroll
        for (int dx = 0; dx < 3; dx++) {
            int xx = x + dx - 1;
            if (xx < 0 || xx > 31) continue;
            acc += vrow[yy * 32 + xx] * wp[dy * 3 + dx];
        }
    }
    float inv = rsqrtf(var[ch] + EPSV) * gam[ch];
    att[idx] += acc * inv + (bet[ch] - mu[ch] * inv);
}

// ---------------------------------------------------------------------------
extern "C" void kernel_launch(void* const* d_in, const int* in_sizes, int n_in,
                              void* d_out, int out_size) {
    const float* x      = (const float*)d_in[0];
    const float* w_qkv  = (const float*)d_in[1];
    const float* g_qkv  = (const float*)d_in[2];
    const float* b_qkv  = (const float*)d_in[3];
    const float* m_qkv  = (const float*)d_in[4];
    const float* v_qkv  = (const float*)d_in[5];
    const float* w_pos  = (const float*)d_in[6];
    const float* g_pos  = (const float*)d_in[7];
    const float* b_pos  = (const float*)d_in[8];
    const float* m_pos  = (const float*)d_in[9];
    const float* v_pos  = (const float*)d_in[10];
    const float* w_proj = (const float*)d_in[11];
    const float* g_proj = (const float*)d_in[12];
    const float* b_proj = (const float*)d_in[13];
    const float* m_proj = (const float*)d_in[14];
    const float* v_proj = (const float*)d_in[15];
    float* out = (float*)d_out;

    float* qkv_buf = nullptr;
    float* att_buf = nullptr;
    __nv_bfloat16* kv_bf = nullptr;
    cudaGetSymbolAddress((void**)&qkv_buf, g_qkv_buf);
    cudaGetSymbolAddress((void**)&att_buf, g_att_buf);
    cudaGetSymbolAddress((void**)&kv_bf, g_kv_bf);

    // 1) QKV GEMM + BN (tensor-core) + kT/v bf16 plane emission
    gemm_bn_kernel<<<dim3(NPIX / 128, HQKV / 64, NB), 256>>>(
        w_qkv, x, qkv_buf, HQKV, g_qkv, b_qkv, m_qkv, v_qkv, kv_bf);

    // 2) Attention -> att_buf (512 threads, 1 q-tile/warp, 8 warps/SMSP)
    attn_kernel<<<512, 512>>>(qkv_buf, kv_bf, att_buf);

    // 3) Depthwise conv + BN, add into att_buf
    pos_conv_kernel<<<(NB * DIMC * NPIX) / 256, 256>>>(
        qkv_buf, att_buf, w_pos, g_pos, b_pos, m_pos, v_pos);

    // 4) Proj GEMM + BN (tensor-core) -> d_out
    gemm_bn_kernel<<<dim3(NPIX / 128, DIMC / 64, NB), 256>>>(
        w_proj, att_buf, out, DIMC, g_proj, b_proj, m_proj, v_proj, nullptr);
}

// round 17
// speedup vs baseline: 1.0636x; 1.0636x over previous
#include <cuda_runtime.h>
#include <cuda_bf16.h>
#include <math.h>

#define DIMC 256
#define NHEADS 8
#define HEADD 32
#define KEYD 16
#define HQKV 512
#define NB 16
#define NPIX 1024
#define EPSV 1e-5f
// score scale folded with log2(e): softmax computed in exp2 domain
#define ATTN_SCALE_LOG2 (0.25f * 1.44269504088896f)

// Scratch (allocation-free rule: __device__ globals)
__device__ float g_qkv_buf[(size_t)NB * HQKV * NPIX];   // 33.5 MB: qkv[b][o][p]
__device__ float g_att_buf[(size_t)NB * DIMC * NPIX];   // 16.8 MB
// Per (b,h) plane (64*NPIX bf16):
//   [0:16384)      kT_hi [1024 pix][16 dims]
//   [16384:32768)  kT_lo [1024 pix][16 dims]
//   [32768:65536)  v_hi  [32 dims][1024 pix]
__device__ __nv_bfloat16 g_kv_bf[(size_t)NB * NHEADS * 64 * NPIX];

// ---------------------------------------------------------------------------
#define MMA16816(c, a, b0v, b1v)                                              \
    asm volatile(                                                             \
        "mma.sync.aligned.m16n8k16.row.col.f32.bf16.bf16.f32 "                \
        "{%0,%1,%2,%3}, {%4,%5,%6,%7}, {%8,%9}, {%0,%1,%2,%3};"               \
        : "+f"((c)[0]), "+f"((c)[1]), "+f"((c)[2]), "+f"((c)[3])              \
        : "r"((a)[0]), "r"((a)[1]), "r"((a)[2]), "r"((a)[3]),                 \
          "r"(b0v), "r"(b1v))

// D = A*B + Z (separate zero source quad; removes per-tile accumulator init)
#define MMA16816_Z(d, a, b0v, b1v, z)                                         \
    asm volatile(                                                             \
        "mma.sync.aligned.m16n8k16.row.col.f32.bf16.bf16.f32 "                \
        "{%0,%1,%2,%3}, {%4,%5,%6,%7}, {%8,%9}, {%10,%11,%12,%13};"           \
        : "=f"((d)[0]), "=f"((d)[1]), "=f"((d)[2]), "=f"((d)[3])              \
        : "r"((a)[0]), "r"((a)[1]), "r"((a)[2]), "r"((a)[3]),                 \
          "r"(b0v), "r"(b1v),                                                 \
          "f"((z)[0]), "f"((z)[1]), "f"((z)[2]), "f"((z)[3]))

// ldmatrix x4: four 8x8 b16 matrices; per-lane address = one 16B row.
#define LDSM_X4(r0, r1, r2, r3, addr32)                                       \
    asm volatile("ldmatrix.sync.aligned.m8n8.x4.shared.b16 {%0,%1,%2,%3}, [%4];" \
        : "=r"(r0), "=r"(r1), "=r"(r2), "=r"(r3) : "r"(addr32))

#define CP_ASYNC16(dst32, src)                                                \
    asm volatile("cp.async.cg.shared.global [%0], [%1], 16;"                  \
                 :: "r"(dst32), "l"(src))
#define CP_COMMIT asm volatile("cp.async.commit_group;")
#define CP_WAIT0  asm volatile("cp.async.wait_group 0;" ::: "memory")

// Split-pack: hi = bf16(v), lo = bf16(v - hi); element0 in low 16 bits.
__device__ __forceinline__ unsigned pack_hi2(float v0, float v1, unsigned& lo_out) {
    __nv_bfloat162 hh, ll;
    hh.x = __float2bfloat16_rn(v0);
    hh.y = __float2bfloat16_rn(v1);
    ll.x = __float2bfloat16_rn(v0 - __bfloat162float(hh.x));
    ll.y = __float2bfloat16_rn(v1 - __bfloat162float(hh.y));
    lo_out = *(unsigned*)&ll;
    return *(unsigned*)&hh;
}

__device__ __forceinline__ unsigned pack_bf16x2(float lo, float hi) {
    unsigned r;
    asm("cvt.rn.bf16x2.f32 %0, %1, %2;" : "=r"(r) : "f"(hi), "f"(lo));
    return r;
}

__device__ __forceinline__ float exp2a(float x) {
    float y;
    asm("ex2.approx.f32 %0, %1;" : "=f"(y) : "f"(x));
    return y;
}

// ---------------------------------------------------------------------------
// Tensor-core GEMM + BN, double-buffered smem, 2 CTAs/SM.
// W hi/lo + In hi/lo, 3-MMA split (numerics identical to R13 baseline).
// Fragment loads via ldmatrix.x4: 48 LDS/warp-kstep -> 10 LDSM (L1 relief).
// If kvbuf != nullptr: emits kT hi/lo (transposed) and v hi bf16 planes.
// ---------------------------------------------------------------------------
__global__ void __launch_bounds__(256, 2)
gemm_bn_kernel(const float* __restrict__ W,
               const float* __restrict__ In,
               float* __restrict__ Out,
               int M,
               const float* __restrict__ gam,
               const float* __restrict__ bet,
               const float* __restrict__ mu,
               const float* __restrict__ var,
               __nv_bfloat16* __restrict__ kvbuf) {
    __shared__ __align__(16) __nv_bfloat16 Ws_h[2][64][24], Ws_l[2][64][24];
    __shared__ __align__(16) __nv_bfloat16 Bs_h[2][128][24], Bs_l[2][128][24];

    const int b = blockIdx.z;
    const int oBase = blockIdx.y * 64;
    const int pBase = blockIdx.x * 128;
    const int tid = threadIdx.x;
    const int warp = tid >> 5;
    const int lane = tid & 31;
    const int gr = lane >> 2;
    const int tc = lane & 3;
    const int o0 = (warp >> 1) * 16;
    const int p0 = (warp & 1) * 64;

    const float* inb = In + (size_t)b * DIMC * NPIX;

    const int sw_o = tid >> 2;
    const int sw_c = (tid & 3) * 4;
    const int sb_p = tid & 127;
    const int sb_cp = tid >> 7;

    // ---- ldmatrix per-lane addresses (buffer 0 base; add cur*stride) ----
    // A mats: g0: row o0+r col0 | g1: row o0+8+r col0 | g2: row o0+r col8 | g3: o0+8+r col8
    // B mats: g0: Bs_h row p0+nt*8+r col0 | g1: Bs_h col8 | g2: Bs_l col0 | g3: Bs_l col8
    const int lg = lane >> 3;          // matrix group 0..3
    const int lr = lane & 7;           // row within matrix
    const unsigned aAddrH = (unsigned)__cvta_generic_to_shared(
        &Ws_h[0][o0 + ((lg & 1) ? 8 : 0) + lr][(lg >> 1) * 8]);
    const unsigned aAddrL = (unsigned)__cvta_generic_to_shared(
        &Ws_l[0][o0 + ((lg & 1) ? 8 : 0) + lr][(lg >> 1) * 8]);
    const unsigned bAddrH = (unsigned)__cvta_generic_to_shared(
        &Bs_h[0][p0 + lr][(lg & 1) * 8]);
    const unsigned bAddrL = (unsigned)__cvta_generic_to_shared(
        &Bs_l[0][p0 + lr][(lg & 1) * 8]);
    const unsigned bAddr0 = (lg >= 2) ? bAddrL : bAddrH;

    float wreg[4];
    float inreg[8];

    // ---- prefetch + commit kstep 0 ----
    *(float4*)wreg = *(const float4*)&W[(size_t)(oBase + sw_o) * DIMC + sw_c];
#pragma unroll
    for (int j = 0; j < 4; j++) {
        int c = 2 * (sb_cp + 2 * j);
        inreg[2 * j]     = inb[(size_t)c * NPIX + pBase + sb_p];
        inreg[2 * j + 1] = inb[(size_t)(c + 1) * NPIX + pBase + sb_p];
    }
#pragma unroll
    for (int j = 0; j < 2; j++) {
        unsigned lo, hi = pack_hi2(wreg[2 * j], wreg[2 * j + 1], lo);
        *(unsigned*)&Ws_h[0][sw_o][sw_c + 2 * j] = hi;
        *(unsigned*)&Ws_l[0][sw_o][sw_c + 2 * j] = lo;
    }
#pragma unroll
    for (int j = 0; j < 4; j++) {
        int c = 2 * (sb_cp + 2 * j);
        unsigned lo, hi = pack_hi2(inreg[2 * j], inreg[2 * j + 1], lo);
        *(unsigned*)&Bs_h[0][sb_p][c] = hi;
        *(unsigned*)&Bs_l[0][sb_p][c] = lo;
    }
    __syncthreads();

    float C[8][4];
#pragma unroll
    for (int nt = 0; nt < 8; nt++)
#pragma unroll
        for (int r = 0; r < 4; r++) C[nt][r] = 0.f;

    for (int ks = 0; ks < 16; ks++) {
        const int cur = ks & 1;
        if (ks < 15) {
            int k0 = (ks + 1) * 16;
            *(float4*)wreg = *(const float4*)&W[(size_t)(oBase + sw_o) * DIMC + k0 + sw_c];
#pragma unroll
            for (int j = 0; j < 4; j++) {
                int c = k0 + 2 * (sb_cp + 2 * j);
                inreg[2 * j]     = inb[(size_t)c * NPIX + pBase + sb_p];
                inreg[2 * j + 1] = inb[(size_t)(c + 1) * NPIX + pBase + sb_p];
            }
        }

        // ---- fragment loads via ldmatrix ----
        unsigned ah[4], al[4];
        LDSM_X4(ah[0], ah[1], ah[2], ah[3], aAddrH + cur * 3072);   // 64*24*2
        LDSM_X4(al[0], al[1], al[2], al[3], aAddrL + cur * 3072);
        const unsigned bBase = bAddr0 + cur * 6144;                 // 128*24*2
#pragma unroll
        for (int nt = 0; nt < 8; nt++) {
            unsigned bf[4];   // {bh0, bh1, bl0, bl1}
            LDSM_X4(bf[0], bf[1], bf[2], bf[3], bBase + nt * 384);  // 8 rows * 48B
            MMA16816(C[nt], ah, bf[0], bf[1]);
            MMA16816(C[nt], ah, bf[2], bf[3]);
            MMA16816(C[nt], al, bf[0], bf[1]);
        }

        if (ks < 15) {
            const int nxt = cur ^ 1;
#pragma unroll
            for (int j = 0; j < 2; j++) {
                unsigned lo, hi = pack_hi2(wreg[2 * j], wreg[2 * j + 1], lo);
                *(unsigned*)&Ws_h[nxt][sw_o][sw_c + 2 * j] = hi;
                *(unsigned*)&Ws_l[nxt][sw_o][sw_c + 2 * j] = lo;
            }
#pragma unroll
            for (int j = 0; j < 4; j++) {
                int c = 2 * (sb_cp + 2 * j);
                unsigned lo, hi = pack_hi2(inreg[2 * j], inreg[2 * j + 1], lo);
                *(unsigned*)&Bs_h[nxt][sb_p][c] = hi;
                *(unsigned*)&Bs_l[nxt][sb_p][c] = lo;
            }
            __syncthreads();
        }
    }

    // ---- epilogue: BN + store (+ optional kv plane emission) ----
    const int oG0 = oBase + o0 + gr;
    const int oG1 = oG0 + 8;
    float inv0 = rsqrtf(var[oG0] + EPSV) * gam[oG0];
    float add0 = bet[oG0] - mu[oG0] * inv0;
    float inv1 = rsqrtf(var[oG1] + EPSV) * gam[oG1];
    float add1 = bet[oG1] - mu[oG1] * inv1;

#pragma unroll
    for (int nt = 0; nt < 8; nt++) {
        int p = pBase + p0 + nt * 8 + 2 * tc;
        float2 r0, r1;
        r0.x = C[nt][0] * inv0 + add0;
        r0.y = C[nt][1] * inv0 + add0;
        r1.x = C[nt][2] * inv1 + add1;
        r1.y = C[nt][3] * inv1 + add1;
        *(float2*)&Out[((size_t)b * M + oG0) * NPIX + p] = r0;
        *(float2*)&Out[((size_t)b * M + oG1) * NPIX + p] = r1;

        if (kvbuf != nullptr) {
#pragma unroll
            for (int rr = 0; rr < 2; rr++) {
                int o = rr ? oG1 : oG0;
                float vx = rr ? r1.x : r0.x;
                float vy = rr ? r1.y : r0.y;
                int r64 = o & 63;
                if (r64 >= 16) {
                    int h = o >> 6;
                    __nv_bfloat16* hb = kvbuf + ((size_t)b * NHEADS + h) * (64 * NPIX);
                    if (r64 >= 32) {          // v: hi plane [32][1024]
                        unsigned hv = pack_bf16x2(vx, vy);
                        *(unsigned*)&hb[32768 + (size_t)(r64 - 32) * NPIX + p] = hv;
                    } else {                  // k: transposed hi/lo planes [1024][16]
                        int d = r64 - 16;
                        __nv_bfloat16 h0 = __float2bfloat16_rn(vx);
                        __nv_bfloat16 l0 = __float2bfloat16_rn(vx - __bfloat162float(h0));
                        __nv_bfloat16 h1 = __float2bfloat16_rn(vy);
                        __nv_bfloat16 l1 = __float2bfloat16_rn(vy - __bfloat162float(h1));
                        hb[(size_t)p * 16 + d] = h0;
                        hb[(size_t)(p + 1) * 16 + d] = h1;
                        hb[16384 + (size_t)p * 16 + d] = l0;
                        hb[16384 + (size_t)(p + 1) * 16 + d] = l1;
                    }
                }
            }
        }
    }
}

// ---------------------------------------------------------------------------
// Attention (R13 structure, best known: 209.4). No online softmax (bounded
// scores). 64-key double-buffered chunks, cp.async staging, 8 warps,
// 2 q-tiles/warp, per-16-key interleaved QK/exp2/pack/AV blocks.
// ---------------------------------------------------------------------------
struct KVBuf {
    __nv_bfloat16 Ks_h[64][24];   // 3072 B
    __nv_bfloat16 Ks_l[64][24];   // 3072 B
    __nv_bfloat16 Vt_h[32][72];   // 4608 B
};
#define KVBUF_BYTES 10752

__global__ void __launch_bounds__(256, 2)
attn_kernel(const float* __restrict__ qkv,
            const __nv_bfloat16* __restrict__ kvbf,
            float* __restrict__ att) {
    __shared__ __align__(16) char smem_raw[KVBUF_BYTES + 16 * 256 * 4];
    KVBuf* bufs[2];
    bufs[0] = (KVBuf*)smem_raw;
    bufs[1] = (KVBuf*)(smem_raw + KVBUF_BYTES);
    float (*Qs)[256] = (float(*)[256])(smem_raw + KVBUF_BYTES);   // alias buf 1

    const int blk = blockIdx.x;      // 0..511
    const int bh = blk >> 2;
    const int qq = blk & 3;
    const int b = bh >> 3;
    const int h = bh & 7;
    const float* base = qkv + ((size_t)b * HQKV + h * 64) * NPIX;
    const __nv_bfloat16* kvh = kvbf + ((size_t)b * NHEADS + h) * (64 * NPIX);
    float* ob = att + ((size_t)b * DIMC + h * HEADD) * NPIX;

    const int tid = threadIdx.x;
    const int warp = tid >> 5;
    const int lane = tid & 31;
    const int gr = lane >> 2;
    const int tc = lane & 3;
    const int qBase = qq * 256;

    // cp.async task mapping (per chunk: 2 x 16B per thread)
    const int kkey = (tid & 127) >> 1;        // key 0..63
    const int kho = (tid & 1) * 8;            // dim half 0/8
    const int vd = tid >> 3;                  // v dim 0..31
    const int vg = tid & 7;                   // key granule 0..7

    // ---- issue chunk 0 into buf0 (doesn't touch Qs alias = buf1) ----
    {
        const __nv_bfloat16* ksrc = kvh + ((tid < 128) ? 0 : 16384)
                                  + (size_t)kkey * 16 + kho;
        unsigned kdst = (unsigned)__cvta_generic_to_shared(
            (tid < 128) ? &bufs[0]->Ks_h[kkey][kho] : &bufs[0]->Ks_l[kkey][kho]);
        CP_ASYNC16(kdst, ksrc);
        unsigned vdst = (unsigned)__cvta_generic_to_shared(&bufs[0]->Vt_h[vd][vg * 8]);
        CP_ASYNC16(vdst, kvh + 32768 + (size_t)vd * NPIX + vg * 8);
        CP_COMMIT;
    }

    // ---- stage Q (scaled into exp2 domain) into aliased region ----
    for (int idx = tid; idx < 16 * 256; idx += 256) {
        int c = idx >> 8, p = idx & 255;
        Qs[c][p] = base[c * NPIX + qBase + p] * ATTN_SCALE_LOG2;
    }
    __syncthreads();

    // ---- Q fragments (bf16 hi only) ----
    unsigned qf[2][4];
#pragma unroll
    for (int qt = 0; qt < 2; qt++) {
        int q0 = warp * 32 + qt * 16 + gr;
#pragma unroll
        for (int r = 0; r < 4; r++) {
            int row = q0 + ((r & 1) ? 8 : 0);
            int k0 = 2 * tc + ((r & 2) ? 8 : 0);
            qf[qt][r] = pack_bf16x2(Qs[k0][row], Qs[k0 + 1][row]);
        }
    }
    CP_WAIT0;
    __syncthreads();   // chunk0 visible; all warps done reading Qs

    float zq[4] = {0.f, 0.f, 0.f, 0.f};
    float lp[2][2];     // per-thread partial sum of P, [qtile][row half]
    float O[2][4][4];
#pragma unroll
    for (int qt = 0; qt < 2; qt++) {
        lp[qt][0] = 0.f; lp[qt][1] = 0.f;
#pragma unroll
        for (int dt = 0; dt < 4; dt++)
#pragma unroll
            for (int r = 0; r < 4; r++) O[qt][dt][r] = 0.f;
    }

    for (int kb = 0; kb < 16; kb++) {
        const KVBuf* cb = bufs[kb & 1];
        const bool more = (kb < 15);
        // ---- issue next chunk into other buffer (async, overlaps MMA) ----
        if (more) {
            KVBuf* nb = bufs[(kb + 1) & 1];
            const size_t koff = (size_t)((kb + 1) * 64 + kkey) * 16 + kho;
            const __nv_bfloat16* ksrc = kvh + ((tid < 128) ? 0 : 16384) + koff;
            unsigned kdst = (unsigned)__cvta_generic_to_shared(
                (tid < 128) ? &nb->Ks_h[kkey][kho] : &nb->Ks_l[kkey][kho]);
            CP_ASYNC16(kdst, ksrc);
            unsigned vdst = (unsigned)__cvta_generic_to_shared(&nb->Vt_h[vd][vg * 8]);
            CP_ASYNC16(vdst, kvh + 32768 + (size_t)vd * NPIX + (kb + 1) * 64 + vg * 8);
            CP_COMMIT;
        }

        // ---- 4 independent 16-key blocks: QK -> exp2 -> pack -> AV ----
#pragma unroll
        for (int ks = 0; ks < 4; ks++) {
            float S[2][2][4];   // [qt][j][reg]
#pragma unroll
            for (int j = 0; j < 2; j++) {
                const int krow = (2 * ks + j) * 8 + gr;
                unsigned bh0 = *(const unsigned*)&cb->Ks_h[krow][2 * tc];
                unsigned bh1 = *(const unsigned*)&cb->Ks_h[krow][2 * tc + 8];
                unsigned bl0 = *(const unsigned*)&cb->Ks_l[krow][2 * tc];
                unsigned bl1 = *(const unsigned*)&cb->Ks_l[krow][2 * tc + 8];
#pragma unroll
                for (int qt = 0; qt < 2; qt++) {
                    MMA16816_Z(S[qt][j], qf[qt], bh0, bh1, zq);
                    MMA16816(S[qt][j], qf[qt], bl0, bl1);
                }
            }

            unsigned ph[2][4];
#pragma unroll
            for (int qt = 0; qt < 2; qt++) {
#pragma unroll
                for (int j = 0; j < 2; j++) {
                    S[qt][j][0] = exp2a(S[qt][j][0]);
                    S[qt][j][1] = exp2a(S[qt][j][1]);
                    S[qt][j][2] = exp2a(S[qt][j][2]);
                    S[qt][j][3] = exp2a(S[qt][j][3]);
                    lp[qt][0] += S[qt][j][0] + S[qt][j][1];
                    lp[qt][1] += S[qt][j][2] + S[qt][j][3];
                }
                ph[qt][0] = pack_bf16x2(S[qt][0][0], S[qt][0][1]);
                ph[qt][1] = pack_bf16x2(S[qt][0][2], S[qt][0][3]);
                ph[qt][2] = pack_bf16x2(S[qt][1][0], S[qt][1][1]);
                ph[qt][3] = pack_bf16x2(S[qt][1][2], S[qt][1][3]);
            }

#pragma unroll
            for (int dt = 0; dt < 4; dt++) {
                const int dr = dt * 8 + gr;
                const int kc = ks * 16 + 2 * tc;
                unsigned vh0 = *(const unsigned*)&cb->Vt_h[dr][kc];
                unsigned vh1 = *(const unsigned*)&cb->Vt_h[dr][kc + 8];
                MMA16816(O[0][dt], ph[0], vh0, vh1);
                MMA16816(O[1][dt], ph[1], vh0, vh1);
            }
        }

        // ---- wait for next chunk copies, then flip ----
        if (more) {
            CP_WAIT0;
            __syncthreads();
        }
    }

    // ---- epilogue: one shfl-reduce of l per row, normalize, store ----
#pragma unroll
    for (int qt = 0; qt < 2; qt++) {
        float l0 = lp[qt][0], l1 = lp[qt][1];
        l0 += __shfl_xor_sync(0xffffffffu, l0, 1);
        l0 += __shfl_xor_sync(0xffffffffu, l0, 2);
        l1 += __shfl_xor_sync(0xffffffffu, l1, 1);
        l1 += __shfl_xor_sync(0xffffffffu, l1, 2);
        float r0 = 1.f / l0;
        float r1 = 1.f / l1;
        int q0 = qBase + warp * 32 + qt * 16 + gr;
        int q1 = q0 + 8;
#pragma unroll
        for (int dt = 0; dt < 4; dt++) {
            int d = dt * 8 + 2 * tc;
            ob[(size_t)d * NPIX + q0]       = O[qt][dt][0] * r0;
            ob[(size_t)(d + 1) * NPIX + q0] = O[qt][dt][1] * r0;
            ob[(size_t)d * NPIX + q1]       = O[qt][dt][2] * r1;
            ob[(size_t)(d + 1) * NPIX + q1] = O[qt][dt][3] * r1;
        }
    }
}

// ---------------------------------------------------------------------------
// Depthwise 3x3 conv on v_img + BN, added into attended buffer in-place.
// ---------------------------------------------------------------------------
__global__ void pos_conv_kernel(const float* __restrict__ qkv,
                                float* __restrict__ att,
                                const float* __restrict__ wpos,
                                const float* __restrict__ gam,
                                const float* __restrict__ bet,
                                const float* __restrict__ mu,
                                const float* __restrict__ var) {
    int idx = blockIdx.x * blockDim.x + threadIdx.x;
    if (idx >= NB * DIMC * NPIX) return;
    int p = idx & 1023;
    int ch = (idx >> 10) & 255;
    int b = idx >> 18;
    int y = p >> 5, x = p & 31;
    int o = ((ch >> 5) * 64) + 32 + (ch & 31);
    const float* vrow = qkv + ((size_t)b * HQKV + o) * NPIX;
    const float* wp = wpos + ch * 9;

    float acc = 0.f;
#pragma unroll
    for (int dy = 0; dy < 3; dy++) {
        int yy = y + dy - 1;
        if (yy < 0 || yy > 31) continue;
#pragma unroll
        for (int dx = 0; dx < 3; dx++) {
            int xx = x + dx - 1;
            if (xx < 0 || xx > 31) continue;
            acc += vrow[yy * 32 + xx] * wp[dy * 3 + dx];
        }
    }
    float inv = rsqrtf(var[ch] + EPSV) * gam[ch];
    att[idx] += acc * inv + (bet[ch] - mu[ch] * inv);
}

// ---------------------------------------------------------------------------
extern "C" void kernel_launch(void* const* d_in, const int* in_sizes, int n_in,
                              void* d_out, int out_size) {
    const float* x      = (const float*)d_in[0];
    const float* w_qkv  = (const float*)d_in[1];
    const float* g_qkv  = (const float*)d_in[2];
    const float* b_qkv  = (const float*)d_in[3];
    const float* m_qkv  = (const float*)d_in[4];
    const float* v_qkv  = (const float*)d_in[5];
    const float* w_pos  = (const float*)d_in[6];
    const float* g_pos  = (const float*)d_in[7];
    const float* b_pos  = (const float*)d_in[8];
    const float* m_pos  = (const float*)d_in[9];
    const float* v_pos  = (const float*)d_in[10];
    const float* w_proj = (const float*)d_in[11];
    const float* g_proj = (const float*)d_in[12];
    const float* b_proj = (const float*)d_in[13];
    const float* m_proj = (const float*)d_in[14];
    const float* v_proj = (const float*)d_in[15];
    float* out = (float*)d_out;

    float* qkv_buf = nullptr;
    float* att_buf = nullptr;
    __nv_bfloat16* kv_bf = nullptr;
    cudaGetSymbolAddress((void**)&qkv_buf, g_qkv_buf);
    cudaGetSymbolAddress((void**)&att_buf, g_att_buf);
    cudaGetSymbolAddress((void**)&kv_bf, g_kv_bf);

    // 1) QKV GEMM + BN (tensor-core, ldmatrix frags) + kT/v bf16 plane emission
    gemm_bn_kernel<<<dim3(NPIX / 128, HQKV / 64, NB), 256>>>(
        w_qkv, x, qkv_buf, HQKV, g_qkv, b_qkv, m_qkv, v_qkv, kv_bf);

    // 2) Attention -> att_buf (R13 best-known structure)
    attn_kernel<<<512, 256>>>(qkv_buf, kv_bf, att_buf);

    // 3) Depthwise conv + BN, add into att_buf
    pos_conv_kernel<<<(NB * DIMC * NPIX) / 256, 256>>>(
        qkv_buf, att_buf, w_pos, g_pos, b_pos, m_pos, v_pos);

    // 4) Proj GEMM + BN (tensor-core, ldmatrix frags) -> d_out
    gemm_bn_kernel<<<dim3(NPIX / 128, DIMC / 64, NB), 256>>>(
        w_proj, att_buf, out, DIMC, g_proj, b_proj, m_proj, v_proj, nullptr);
}